// round 6
// baseline (speedup 1.0000x reference)
#include <cuda_runtime.h>
#include <math_constants.h>

// NonMaxSuppression: 3x3 max-pool NMS mask on (8,1,2048,2048) fp32.
// out[y][x] = 1.0f iff in[y][x] == max3x3(in, y, x)  (pad -inf)
//             && in[y][x] >= 0.6f
//             && 10 <= y < H-10 && 10 <= x < W-10
//
// R6: R2 structure (best so far: 42.6us kernel, DRAM 67%). Occupancy sweep:
//   64 regs /  8 blocks (R2): in-flight ~= BDP, latency-marginal.
//   32 regs / 16 blocks (R5): spills (L1 48%, fma 9.4%) -> slower.
// This round: 39-reg budget via __launch_bounds__(128, 13) -> 52 warps/SM,
// ~1.6x R2's in-flight bytes, with enough regs for the ~36-float live set.

#define H 2048
#define W 2048
#define ROWS 32
#define REP_THR 0.6f
#define BORDER 10

__device__ __forceinline__ float4 hmax4(float4 v, float l, float r) {
    float4 h;
    h.x = fmaxf(l,   fmaxf(v.x, v.y));
    h.y = fmaxf(v.x, fmaxf(v.y, v.z));
    h.z = fmaxf(v.y, fmaxf(v.z, v.w));
    h.w = fmaxf(v.z, fmaxf(v.w, r));
    return h;
}

struct Row {
    float4 v;   // 4 pixels
    float  l;   // left halo  (lane 0 only)
    float  r;   // right halo (lane 31 only)
};

__global__ __launch_bounds__(128, 13)
void nms_kernel(const float* __restrict__ in, float* __restrict__ out) {
    const int lane = threadIdx.x;                              // 0..31
    const int seg  = blockIdx.x * blockDim.y + threadIdx.y;    // 0..15
    const int b    = blockIdx.z;
    const int y0   = blockIdx.y * ROWS;

    const int x4 = seg * 128 + lane * 4;

    const float* img = in  + (size_t)b * H * W;
    float*       o   = out + (size_t)b * H * W;

    const bool edge_l = (lane == 0  && x4 > 0);
    const bool edge_r = (lane == 31 && x4 + 4 < W);

    auto load_raw = [&](int y) -> Row {
        Row p;
        int yy = y < 0 ? 0 : (y >= H ? H - 1 : y);
        const float* row = img + (size_t)yy * W;
        p.v = *reinterpret_cast<const float4*>(row + x4);
        p.l = edge_l ? row[x4 - 1] : -CUDART_INF_F;
        p.r = edge_r ? row[x4 + 4] : -CUDART_INF_F;
        return p;
    };

    auto consume = [&](const Row& p) -> float4 {
        float l = __shfl_up_sync(0xffffffffu,   p.v.w, 1);
        float r = __shfl_down_sync(0xffffffffu, p.v.x, 1);
        if (lane == 0)  l = p.l;
        if (lane == 31) r = p.r;
        return hmax4(p.v, l, r);
    };

    // Prologue: rows y0-1, y0 consumed; row y0+1 left in flight.
    Row p_m = load_raw(y0 - 1);
    Row p_c = load_raw(y0);
    Row p_n = load_raw(y0 + 1);

    float4 hm_m  = consume(p_m);
    float4 hm_c  = consume(p_c);
    float4 v_cur = p_c.v;

    const bool bx0 = (x4 + 0 >= BORDER) && (x4 + 0 < W - BORDER);
    const bool bx1 = (x4 + 1 >= BORDER) && (x4 + 1 < W - BORDER);
    const bool bx2 = (x4 + 2 >= BORDER) && (x4 + 2 < W - BORDER);
    const bool bx3 = (x4 + 3 >= BORDER) && (x4 + 3 < W - BORDER);

    #pragma unroll 2
    for (int y = y0; y < y0 + ROWS; ++y) {
        // Next row's load first — independent of everything below.
        Row p_nn = load_raw(y + 2);

        // Consume the row loaded last iteration.
        float4 hm_p = consume(p_n);

        const bool by = (y >= BORDER) && (y < H - BORDER);

        float4 res;
        {
            float m;
            m = fmaxf(hm_m.x, fmaxf(hm_c.x, hm_p.x));
            res.x = (by && bx0 && v_cur.x >= REP_THR && v_cur.x == m) ? 1.0f : 0.0f;
            m = fmaxf(hm_m.y, fmaxf(hm_c.y, hm_p.y));
            res.y = (by && bx1 && v_cur.y >= REP_THR && v_cur.y == m) ? 1.0f : 0.0f;
            m = fmaxf(hm_m.z, fmaxf(hm_c.z, hm_p.z));
            res.z = (by && bx2 && v_cur.z >= REP_THR && v_cur.z == m) ? 1.0f : 0.0f;
            m = fmaxf(hm_m.w, fmaxf(hm_c.w, hm_p.w));
            res.w = (by && bx3 && v_cur.w >= REP_THR && v_cur.w == m) ? 1.0f : 0.0f;
        }

        __stcs(reinterpret_cast<float4*>(o + (size_t)y * W + x4), res);

        hm_m  = hm_c;
        hm_c  = hm_p;
        v_cur = p_n.v;
        p_n   = p_nn;
    }
}

extern "C" void kernel_launch(void* const* d_in, const int* in_sizes, int n_in,
                              void* d_out, int out_size) {
    const float* in = (const float*)d_in[0];
    float* out = (float*)d_out;
    (void)in_sizes; (void)n_in; (void)out_size;

    dim3 block(32, 4);                 // 4 warps, each owns a 128-col segment
    dim3 grid(16 / 4, H / ROWS, 8);    // 4 x 64 x 8 = 2048 blocks
    nms_kernel<<<grid, block>>>(in, out);
}